// round 13
// baseline (speedup 1.0000x reference)
#include <cuda_runtime.h>

#define NMAX 100000
#define EMAX 3200000

// -------- device scratch (no allocations allowed) --------
// g_deg and g_bsum are zeroed at the END of each call (k_logits); zero-init at load.
__device__ int   g_deg[NMAX];          // per-node in-degree (excl self-loop)
__device__ int   g_start[NMAX];        // CSR row start
__device__ int   g_cursor[NMAX];       // fill cursors
__device__ int   g_bsum[512];          // block sums for scan, stored as (sum+1); 0 = not ready
__device__ int   g_adj[EMAX];          // CSR adjacency: src indices grouped by dst
__device__ float g_dinv[NMAX];         // 1/sqrt(deg+1)
__device__ __align__(16) float g_ht1[NMAX * 16];   // raw x@W1, then dinv-scaled
__device__ __align__(16) float g_ht2[NMAX * 16];   // dinv * relu(agg1+b1)
__device__ __align__(8) float2 g_q[NMAX];          // (ht2row.v1, ht2row.v2) per node
__device__ float g_s1[NMAX];           // z . We[:64]
__device__ float g_s2[NMAX];           // z . We[64:]
__device__ float g_v1[16];             // W2 @ We[:64]
__device__ float g_v2[16];             // W2 @ We[64:]
__device__ float g_c1, g_c2;           // b2 . We halves

// -------- degree histogram + (block 0) fold W2/b2 into the edge head --------
__global__ void k_deg_acc(const int* __restrict__ dst, int E, int n,
                          const float* __restrict__ W2, const float* __restrict__ b2,
                          const float* __restrict__ We) {
    if (blockIdx.x == 0) {
        int t = threadIdx.x;
        if (t < 16) {
            float a = 0.f, b = 0.f;
            #pragma unroll
            for (int j = 0; j < 64; j++) {
                float w = W2[t * 64 + j];
                a += w * We[j];
                b += w * We[64 + j];
            }
            g_v1[t] = a;
            g_v2[t] = b;
        } else if (t == 16) {
            float a = 0.f, b = 0.f;
            #pragma unroll
            for (int j = 0; j < 64; j++) {
                a += b2[j] * We[j];
                b += b2[j] * We[64 + j];
            }
            g_c1 = a;
            g_c2 = b;
        }
    }
    int e = blockIdx.x * blockDim.x + threadIdx.x;
    if (e < E) {
        unsigned d = (unsigned)dst[e];
        if (d < (unsigned)n) atomicAdd(&g_deg[d], 1);
    }
}

// -------- single-kernel exclusive scan: parallel-poll lookback --------
// All 391 blocks are co-resident (256 thr/block, low regs), so polling lower
// block ids cannot deadlock. g_bsum[b] holds (blocksum+1); 0 means not ready.
// Single-word publish => no fence needed between value and flag.
__global__ void k_scan(int n) {
    __shared__ int s[256];
    __shared__ int red[256];
    int tid = threadIdx.x;
    int b = blockIdx.x;
    int i = b * 256 + tid;
    int deg = (i < n) ? g_deg[i] : 0;
    s[tid] = deg;
    __syncthreads();
    #pragma unroll
    for (int o = 1; o < 256; o <<= 1) {
        int t = (tid >= o) ? s[tid - o] : 0;
        __syncthreads();
        s[tid] += t;
        __syncthreads();
    }
    int incl = s[tid];
    if (tid == 255)
        *((volatile int*)&g_bsum[b]) = s[255] + 1;   // publish (sum+1)

    // parallel poll of all predecessor blocks
    int partial = 0;
    for (int j = tid; j < b; j += 256) {
        int v;
        while ((v = *((volatile int*)&g_bsum[j])) == 0) { }
        partial += v - 1;
    }
    red[tid] = partial;
    __syncthreads();
    #pragma unroll
    for (int o = 128; o > 0; o >>= 1) {
        if (tid < o) red[tid] += red[tid + o];
        __syncthreads();
    }
    int run = red[0];
    if (i < n) {
        int st = run + incl - deg;   // exclusive prefix
        g_start[i] = st;
        g_cursor[i] = st;
        g_dinv[i] = rsqrtf((float)deg + 1.0f);   // +1 = self-loop
    }
}

__global__ void k_fill(const int* __restrict__ src, const int* __restrict__ dst,
                       int E, int n) {
    int e = blockIdx.x * blockDim.x + threadIdx.x;
    if (e >= E) return;
    unsigned s = (unsigned)src[e];
    unsigned d = (unsigned)dst[e];
    if (s >= (unsigned)n || d >= (unsigned)n) return;
    int slot = atomicAdd(&g_cursor[d], 1);
    g_adj[slot] = (int)s;
}

// -------- GEMM1: ht1 = x @ W1 (raw), coalesced via smem x-tiles --------
__global__ void __launch_bounds__(256) k_gemm1(const float* __restrict__ x,
                                               const float* __restrict__ W1, int n) {
    __shared__ float4 Wss[2048];        // W1[k][4q..4q+3] (32 KB)
    __shared__ float  xs[256 * 12];     // 12 KB padded x tile
    for (int i = threadIdx.x; i < 2048; i += 256)
        Wss[i] = ((const float4*)W1)[i];

    int row0 = blockIdx.x * 256;
    int tid = threadIdx.x;

    float acc[16];
    #pragma unroll
    for (int j = 0; j < 16; j++) acc[j] = 0.f;

    const float4* xq = (const float4*)x;

    for (int kt = 0; kt < 64; kt++) {
        __syncthreads();
        #pragma unroll
        for (int m = 0; m < 2; m++) {
            int idx = tid + m * 256;
            int rr = idx >> 1, q = idx & 1;
            int grow = row0 + rr;
            float4 v = make_float4(0.f, 0.f, 0.f, 0.f);
            if (grow < n) v = __ldg(&xq[(size_t)grow * 128 + kt * 2 + q]);
            *(float4*)&xs[rr * 12 + q * 4] = v;
        }
        __syncthreads();

        float4 x0 = *(const float4*)&xs[tid * 12];
        float4 x1 = *(const float4*)&xs[tid * 12 + 4];
        float xv[8] = {x0.x, x0.y, x0.z, x0.w, x1.x, x1.y, x1.z, x1.w};
        #pragma unroll
        for (int kk = 0; kk < 8; kk++) {
            int k = kt * 8 + kk;
            float xsv = xv[kk];
            #pragma unroll
            for (int q2 = 0; q2 < 4; q2++) {
                float4 w = Wss[k * 4 + q2];
                acc[q2 * 4 + 0] = fmaf(xsv, w.x, acc[q2 * 4 + 0]);
                acc[q2 * 4 + 1] = fmaf(xsv, w.y, acc[q2 * 4 + 1]);
                acc[q2 * 4 + 2] = fmaf(xsv, w.z, acc[q2 * 4 + 2]);
                acc[q2 * 4 + 3] = fmaf(xsv, w.w, acc[q2 * 4 + 3]);
            }
        }
    }

    int r = row0 + tid;
    if (r < n) {
        float4* hp = (float4*)(g_ht1 + (size_t)r * 16);
        #pragma unroll
        for (int q = 0; q < 4; q++)
            hp[q] = make_float4(acc[q * 4 + 0], acc[q * 4 + 1],
                                acc[q * 4 + 2], acc[q * 4 + 3]);
    }
}

// -------- scale: ht1 *= dinv (side stream; overlaps k_fill) --------
__global__ void k_scale(int n) {
    int i = blockIdx.x * blockDim.x + threadIdx.x;
    if (i >= n) return;
    float di = g_dinv[i];
    float4* p = (float4*)(g_ht1 + (size_t)i * 16);
    #pragma unroll
    for (int q = 0; q < 4; q++) {
        float4 v = p[q];
        p[q] = make_float4(v.x * di, v.y * di, v.z * di, v.w * di);
    }
}

// -------- feature-parallel gather core: 16 lanes per node (R10 best form) --------
__device__ __forceinline__ float gather_feat(const float* __restrict__ ht,
                                             int d, int l) {
    float acc = __ldg(&ht[(d << 4) | l]);   // self-loop term
    int e = g_start[d];
    int end = e + g_deg[d];
    for (; e + 7 < end; e += 8) {
        int s0 = __ldg(&g_adj[e]);
        int s1 = __ldg(&g_adj[e + 1]);
        int s2 = __ldg(&g_adj[e + 2]);
        int s3 = __ldg(&g_adj[e + 3]);
        int s4 = __ldg(&g_adj[e + 4]);
        int s5 = __ldg(&g_adj[e + 5]);
        int s6 = __ldg(&g_adj[e + 6]);
        int s7 = __ldg(&g_adj[e + 7]);
        float v0 = __ldg(&ht[(s0 << 4) | l]);
        float v1 = __ldg(&ht[(s1 << 4) | l]);
        float v2 = __ldg(&ht[(s2 << 4) | l]);
        float v3 = __ldg(&ht[(s3 << 4) | l]);
        float v4 = __ldg(&ht[(s4 << 4) | l]);
        float v5 = __ldg(&ht[(s5 << 4) | l]);
        float v6 = __ldg(&ht[(s6 << 4) | l]);
        float v7 = __ldg(&ht[(s7 << 4) | l]);
        acc += ((v0 + v1) + (v2 + v3)) + ((v4 + v5) + (v6 + v7));
    }
    for (; e + 1 < end; e += 2) {
        int s0 = __ldg(&g_adj[e]);
        int s1 = __ldg(&g_adj[e + 1]);
        acc += __ldg(&ht[(s0 << 4) | l]) + __ldg(&ht[(s1 << 4) | l]);
    }
    if (e < end) {
        int s0 = __ldg(&g_adj[e]);
        acc += __ldg(&ht[(s0 << 4) | l]);
    }
    return acc;
}

// -------- gather layer 1: ht2 = dinv*relu(dinv*sum + b1); also emit q=(h.v1,h.v2) ----
__global__ void k_gather1(const float* __restrict__ b1, int n) {
    int t = blockIdx.x * blockDim.x + threadIdx.x;
    int d = t >> 4, l = t & 15;
    bool valid = (d < n);
    int dd = valid ? d : 0;
    float acc = gather_feat(g_ht1, dd, l);
    float di = g_dinv[dd];
    float h = fmaxf(fmaf(acc, di, __ldg(&b1[l])), 0.f) * di;
    if (valid) g_ht2[(dd << 4) | l] = h;

    // per-node head scalars: q1 = h.v1, q2 = h.v2 (16-lane shuffle reduce)
    float p1 = h * g_v1[l];
    float p2 = h * g_v2[l];
    #pragma unroll
    for (int o = 1; o < 16; o <<= 1) {
        p1 += __shfl_xor_sync(0xffffffffu, p1, o);
        p2 += __shfl_xor_sync(0xffffffffu, p2, o);
    }
    if (valid && l == 0) g_q[d] = make_float2(p1, p2);
}

// -------- scalar head gather: s1/s2 from q table (runs concurrent with gather2) ----
__global__ void k_heads(int n) {
    int d = blockIdx.x * blockDim.x + threadIdx.x;
    if (d >= n) return;
    float2 qd = __ldg(&g_q[d]);
    float a1 = qd.x, a2 = qd.y;
    int e = g_start[d];
    int end = e + g_deg[d];
    for (; e + 3 < end; e += 4) {
        int s0 = __ldg(&g_adj[e]);
        int s1 = __ldg(&g_adj[e + 1]);
        int s2 = __ldg(&g_adj[e + 2]);
        int s3 = __ldg(&g_adj[e + 3]);
        float2 v0 = __ldg(&g_q[s0]);
        float2 v1 = __ldg(&g_q[s1]);
        float2 v2 = __ldg(&g_q[s2]);
        float2 v3 = __ldg(&g_q[s3]);
        a1 += (v0.x + v1.x) + (v2.x + v3.x);
        a2 += (v0.y + v1.y) + (v2.y + v3.y);
    }
    for (; e < end; e++) {
        int s0 = __ldg(&g_adj[e]);
        float2 v0 = __ldg(&g_q[s0]);
        a1 += v0.x;
        a2 += v0.y;
    }
    float di = g_dinv[d];
    g_s1[d] = fmaf(a1, di, g_c1);
    g_s2[d] = fmaf(a2, di, g_c2);
}

// -------- gather layer 2 + z epilogue (no heads here anymore) --------
__global__ void k_gather2(const float* __restrict__ W2, const float* __restrict__ b2,
                          float* __restrict__ z, int n) {
    __shared__ float4 Ws[16 * 16];   // W2[k] column-quads (4 KB)
    __shared__ float4 bs[16];
    for (int i = threadIdx.x; i < 256; i += blockDim.x)
        Ws[i] = ((const float4*)W2)[i];
    if (threadIdx.x < 16)
        bs[threadIdx.x] = ((const float4*)b2)[threadIdx.x];
    __syncthreads();

    int t = blockIdx.x * blockDim.x + threadIdx.x;
    int d = t >> 4, l = t & 15;
    bool valid = (d < n);

    float acc = 0.f;
    if (valid) acc = gather_feat(g_ht2, d, l) * g_dinv[d];

    // broadcast the 16 per-feature sums to every lane of the group
    int base = (threadIdx.x & 31) & 16;   // group's base lane within the warp
    float a[16];
    #pragma unroll
    for (int k = 0; k < 16; k++)
        a[k] = __shfl_sync(0xffffffffu, acc, base + k, 32);

    if (!valid) return;

    // z columns [4l, 4l+4): one float4 per lane, coalesced across the group
    float4 accv = bs[l];
    #pragma unroll
    for (int k = 0; k < 16; k++) {
        float4 w = Ws[k * 16 + l];
        accv.x = fmaf(a[k], w.x, accv.x);
        accv.y = fmaf(a[k], w.y, accv.y);
        accv.z = fmaf(a[k], w.z, accv.z);
        accv.w = fmaf(a[k], w.w, accv.w);
    }
    ((float4*)(z + (size_t)d * 64))[l] = accv;
}

// -------- edge logits: s1[src]+s2[dst]+be ; re-zero g_deg and g_bsum --------
__global__ void k_logits(const int* __restrict__ ps, const int* __restrict__ pd,
                         const int* __restrict__ ns, const int* __restrict__ nd,
                         const float* __restrict__ be, float* __restrict__ out,
                         int P, int Ng, int n) {
    int i = blockIdx.x * blockDim.x + threadIdx.x;
    if (i < n) g_deg[i] = 0;           // prepare next call (invariant: zero at entry)
    if (i < 512) g_bsum[i] = 0;
    if (i >= P + Ng) return;
    unsigned s, d;
    if (i < P) { s = (unsigned)ps[i]; d = (unsigned)pd[i]; }
    else       { s = (unsigned)ns[i - P]; d = (unsigned)nd[i - P]; }
    float v = __ldg(be);
    if (s < (unsigned)n) v += g_s1[s];
    if (d < (unsigned)n) v += g_s2[d];
    out[i] = v;
}

extern "C" void kernel_launch(void* const* d_in, const int* in_sizes, int n_in,
                              void* d_out, int out_size) {
    const float* x  = (const float*)d_in[0];
    const float* W1 = (const float*)d_in[1];
    const float* b1 = (const float*)d_in[2];
    const float* W2 = (const float*)d_in[3];
    const float* b2 = (const float*)d_in[4];
    const float* We = (const float*)d_in[5];
    const float* be = (const float*)d_in[6];
    const int* ei = (const int*)d_in[7];   // edge_index int32 [2, E]
    const int* pe = (const int*)d_in[8];   // pos_edge_index int32 [2, P]
    const int* ne = (const int*)d_in[9];   // neg_edge_index int32 [2, Ng]

    int n  = in_sizes[0] / 512;
    int E  = in_sizes[7] / 2;
    int P  = in_sizes[8] / 2;
    int Ng = in_sizes[9] / 2;

    float* z = (float*)d_out;                 // [n, 64]
    float* logits = z + (size_t)n * 64;       // [P + Ng]

    const int* src = ei;
    const int* dst = ei + E;

    int nb  = (n + 255) / 256;
    int eb  = (E + 255) / 256;
    int gb  = (16 * n + 255) / 256;
    int lb  = (P + Ng + 255) / 256;

    // One-time stream/event setup (outside capture: first call is uncaptured).
    static cudaStream_t s1 = nullptr;
    static cudaEvent_t evFork = nullptr, evScan = nullptr, evScale = nullptr,
                       evG1 = nullptr, evL = nullptr;
    if (s1 == nullptr) {
        cudaStreamCreateWithFlags(&s1, cudaStreamNonBlocking);
        cudaEventCreateWithFlags(&evFork, cudaEventDisableTiming);
        cudaEventCreateWithFlags(&evScan, cudaEventDisableTiming);
        cudaEventCreateWithFlags(&evScale, cudaEventDisableTiming);
        cudaEventCreateWithFlags(&evG1, cudaEventDisableTiming);
        cudaEventCreateWithFlags(&evL, cudaEventDisableTiming);
    }

    // Fork at t=0: GEMM1 (raw h, no dinv dependency) on side stream.
    cudaEventRecord(evFork, 0);
    cudaStreamWaitEvent(s1, evFork, 0);
    k_gemm1<<<nb, 256, 0, s1>>>(x, W1, n);

    // Main stream: CSR build (g_deg/g_bsum zero on entry, invariant).
    k_deg_acc<<<eb, 256>>>(dst, E, n, W2, b2, We);
    k_scan<<<nb, 256>>>(n);
    cudaEventRecord(evScan, 0);               // dinv/starts/cursors ready
    k_fill<<<eb, 256>>>(src, dst, E, n);

    // Side stream: scale (needs gemm1 done + dinv), overlaps fill.
    cudaStreamWaitEvent(s1, evScan, 0);
    k_scale<<<nb, 256, 0, s1>>>(n);
    cudaEventRecord(evScale, s1);

    // Main: gather1 (needs adj from fill [main order] + scaled ht1 [side]).
    cudaStreamWaitEvent(0, evScale, 0);
    k_gather1<<<gb, 256>>>(b1, n);
    cudaEventRecord(evG1, 0);

    // Side: heads + logits, concurrent with gather2 on main.
    cudaStreamWaitEvent(s1, evG1, 0);
    k_heads<<<nb, 256, 0, s1>>>(n);
    k_logits<<<lb, 256, 0, s1>>>(pe, pe + P, ne, ne + Ng, be, logits, P, Ng, n);
    cudaEventRecord(evL, s1);

    // Main: gather2 (z), then join side work before returning.
    k_gather2<<<gb, 256>>>(W2, b2, z, n);
    cudaStreamWaitEvent(0, evL, 0);
}

// round 14
// speedup vs baseline: 1.0786x; 1.0786x over previous
#include <cuda_runtime.h>

#define NMAX 100000
#define EMAX 3200000

// -------- device scratch (no allocations allowed) --------
// g_deg is zeroed at the END of each call (k_logits); zero-init at load.
__device__ int   g_deg[NMAX];          // per-node in-degree (excl self-loop)
__device__ int   g_start[NMAX];        // CSR row start
__device__ int   g_bsum[512];          // block sums for scan
__device__ int   g_rank[EMAX];         // per-edge rank within its dst (from deg_acc)
__device__ int   g_adj[EMAX];          // CSR adjacency: src indices grouped by dst
__device__ float g_dinv[NMAX];         // 1/sqrt(deg+1)
__device__ __align__(16) float g_ht1[NMAX * 16];   // raw x@W1, then dinv-scaled
__device__ __align__(16) float g_ht2[NMAX * 16];   // dinv * relu(agg1+b1)
__device__ float g_s1[NMAX];           // z . We[:64]
__device__ float g_s2[NMAX];           // z . We[64:]
__device__ float g_v1[16];             // W2 @ We[:64]
__device__ float g_v2[16];             // W2 @ We[64:]
__device__ float g_c1, g_c2;           // b2 . We halves

// -------- degree histogram (rank capture) + (block 0) fold W2/b2 head --------
__global__ void k_deg_acc(const int* __restrict__ dst, int E, int n,
                          const float* __restrict__ W2, const float* __restrict__ b2,
                          const float* __restrict__ We) {
    if (blockIdx.x == 0) {
        int t = threadIdx.x;
        if (t < 16) {
            float a = 0.f, b = 0.f;
            #pragma unroll
            for (int j = 0; j < 64; j++) {
                float w = W2[t * 64 + j];
                a += w * We[j];
                b += w * We[64 + j];
            }
            g_v1[t] = a;
            g_v2[t] = b;
        } else if (t == 16) {
            float a = 0.f, b = 0.f;
            #pragma unroll
            for (int j = 0; j < 64; j++) {
                a += b2[j] * We[j];
                b += b2[j] * We[64 + j];
            }
            g_c1 = a;
            g_c2 = b;
        }
    }
    int e = blockIdx.x * blockDim.x + threadIdx.x;
    if (e < E) {
        unsigned d = (unsigned)dst[e];
        if (d < (unsigned)n)
            g_rank[e] = atomicAdd(&g_deg[d], 1);   // rank within dst, coalesced store
    }
}

// per-block exclusive scan of g_deg -> g_start (block-local), totals -> g_bsum
__global__ void k_scan1(int n) {
    __shared__ int s[256];
    int tid = threadIdx.x;
    int i = blockIdx.x * 256 + tid;
    int v = (i < n) ? g_deg[i] : 0;
    s[tid] = v;
    __syncthreads();
    #pragma unroll
    for (int o = 1; o < 256; o <<= 1) {
        int t = (tid >= o) ? s[tid - o] : 0;
        __syncthreads();
        s[tid] += t;
        __syncthreads();
    }
    if (i < n) g_start[i] = s[tid] - v;
    if (tid == 255) g_bsum[blockIdx.x] = s[255];
}

// each block self-computes its prefix over bsum[0..b-1], finalizes starts/dinv
__global__ void k_scan23(int n) {
    __shared__ int red[256];
    int tid = threadIdx.x;
    int b = blockIdx.x;
    int partial = 0;
    for (int j = tid; j < b; j += 256) partial += g_bsum[j];
    red[tid] = partial;
    __syncthreads();
    #pragma unroll
    for (int o = 128; o > 0; o >>= 1) {
        if (tid < o) red[tid] += red[tid + o];
        __syncthreads();
    }
    int run = red[0];
    int i = b * 256 + tid;
    if (i < n) {
        g_start[i] = g_start[i] + run;
        g_dinv[i] = rsqrtf((float)g_deg[i] + 1.0f);   // +1 = self-loop
    }
}

// -------- atomic-free fill: slot = start[dst] + rank[e] --------
__global__ void k_fill(const int* __restrict__ src, const int* __restrict__ dst,
                       int E, int n) {
    int e = blockIdx.x * blockDim.x + threadIdx.x;
    if (e >= E) return;
    unsigned s = (unsigned)src[e];
    unsigned d = (unsigned)dst[e];
    if (s >= (unsigned)n || d >= (unsigned)n) return;
    int slot = __ldg(&g_start[d]) + g_rank[e];
    g_adj[slot] = (int)s;
}

// -------- GEMM1: ht1 = x @ W1 (raw), coalesced via smem x-tiles --------
__global__ void __launch_bounds__(256) k_gemm1(const float* __restrict__ x,
                                               const float* __restrict__ W1, int n) {
    __shared__ float4 Wss[2048];        // W1[k][4q..4q+3] (32 KB)
    __shared__ float  xs[256 * 12];     // 12 KB padded x tile
    for (int i = threadIdx.x; i < 2048; i += 256)
        Wss[i] = ((const float4*)W1)[i];

    int row0 = blockIdx.x * 256;
    int tid = threadIdx.x;

    float acc[16];
    #pragma unroll
    for (int j = 0; j < 16; j++) acc[j] = 0.f;

    const float4* xq = (const float4*)x;

    for (int kt = 0; kt < 64; kt++) {
        __syncthreads();
        #pragma unroll
        for (int m = 0; m < 2; m++) {
            int idx = tid + m * 256;
            int rr = idx >> 1, q = idx & 1;
            int grow = row0 + rr;
            float4 v = make_float4(0.f, 0.f, 0.f, 0.f);
            if (grow < n) v = __ldg(&xq[(size_t)grow * 128 + kt * 2 + q]);
            *(float4*)&xs[rr * 12 + q * 4] = v;
        }
        __syncthreads();

        float4 x0 = *(const float4*)&xs[tid * 12];
        float4 x1 = *(const float4*)&xs[tid * 12 + 4];
        float xv[8] = {x0.x, x0.y, x0.z, x0.w, x1.x, x1.y, x1.z, x1.w};
        #pragma unroll
        for (int kk = 0; kk < 8; kk++) {
            int k = kt * 8 + kk;
            float xsv = xv[kk];
            #pragma unroll
            for (int q2 = 0; q2 < 4; q2++) {
                float4 w = Wss[k * 4 + q2];
                acc[q2 * 4 + 0] = fmaf(xsv, w.x, acc[q2 * 4 + 0]);
                acc[q2 * 4 + 1] = fmaf(xsv, w.y, acc[q2 * 4 + 1]);
                acc[q2 * 4 + 2] = fmaf(xsv, w.z, acc[q2 * 4 + 2]);
                acc[q2 * 4 + 3] = fmaf(xsv, w.w, acc[q2 * 4 + 3]);
            }
        }
    }

    int r = row0 + tid;
    if (r < n) {
        float4* hp = (float4*)(g_ht1 + (size_t)r * 16);
        #pragma unroll
        for (int q = 0; q < 4; q++)
            hp[q] = make_float4(acc[q * 4 + 0], acc[q * 4 + 1],
                                acc[q * 4 + 2], acc[q * 4 + 3]);
    }
}

// -------- scale: ht1 *= dinv (side stream; overlaps k_fill) --------
__global__ void k_scale(int n) {
    int i = blockIdx.x * blockDim.x + threadIdx.x;
    if (i >= n) return;
    float di = g_dinv[i];
    float4* p = (float4*)(g_ht1 + (size_t)i * 16);
    #pragma unroll
    for (int q = 0; q < 4; q++) {
        float4 v = p[q];
        p[q] = make_float4(v.x * di, v.y * di, v.z * di, v.w * di);
    }
}

// -------- feature-parallel gather core: 16 lanes per node (R10 best form) --------
__device__ __forceinline__ float gather_feat(const float* __restrict__ ht,
                                             int d, int l) {
    float acc = __ldg(&ht[(d << 4) | l]);   // self-loop term
    int e = g_start[d];
    int end = e + g_deg[d];
    for (; e + 7 < end; e += 8) {
        int s0 = __ldg(&g_adj[e]);
        int s1 = __ldg(&g_adj[e + 1]);
        int s2 = __ldg(&g_adj[e + 2]);
        int s3 = __ldg(&g_adj[e + 3]);
        int s4 = __ldg(&g_adj[e + 4]);
        int s5 = __ldg(&g_adj[e + 5]);
        int s6 = __ldg(&g_adj[e + 6]);
        int s7 = __ldg(&g_adj[e + 7]);
        float v0 = __ldg(&ht[(s0 << 4) | l]);
        float v1 = __ldg(&ht[(s1 << 4) | l]);
        float v2 = __ldg(&ht[(s2 << 4) | l]);
        float v3 = __ldg(&ht[(s3 << 4) | l]);
        float v4 = __ldg(&ht[(s4 << 4) | l]);
        float v5 = __ldg(&ht[(s5 << 4) | l]);
        float v6 = __ldg(&ht[(s6 << 4) | l]);
        float v7 = __ldg(&ht[(s7 << 4) | l]);
        acc += ((v0 + v1) + (v2 + v3)) + ((v4 + v5) + (v6 + v7));
    }
    for (; e + 1 < end; e += 2) {
        int s0 = __ldg(&g_adj[e]);
        int s1 = __ldg(&g_adj[e + 1]);
        acc += __ldg(&ht[(s0 << 4) | l]) + __ldg(&ht[(s1 << 4) | l]);
    }
    if (e < end) {
        int s0 = __ldg(&g_adj[e]);
        acc += __ldg(&ht[(s0 << 4) | l]);
    }
    return acc;
}

// -------- gather layer 1: ht2 = dinv * relu(dinv*sum + b1) --------
__global__ void k_gather1(const float* __restrict__ b1, int n) {
    int t = blockIdx.x * blockDim.x + threadIdx.x;
    int d = t >> 4, l = t & 15;
    if (d >= n) return;
    float acc = gather_feat(g_ht1, d, l);
    float di = g_dinv[d];
    g_ht2[(d << 4) | l] = fmaxf(fmaf(acc, di, __ldg(&b1[l])), 0.f) * di;
}

// -------- gather layer 2 + fused epilogue: z, s1, s2 (shuffle exchange) --------
__global__ void k_gather2(const float* __restrict__ W2, const float* __restrict__ b2,
                          float* __restrict__ z, int n) {
    __shared__ float4 Ws[16 * 16];   // W2[k] column-quads (4 KB)
    __shared__ float4 bs[16];
    __shared__ float vs1[16], vs2[16];
    for (int i = threadIdx.x; i < 256; i += blockDim.x)
        Ws[i] = ((const float4*)W2)[i];
    if (threadIdx.x < 16) {
        bs[threadIdx.x] = ((const float4*)b2)[threadIdx.x];
        vs1[threadIdx.x] = g_v1[threadIdx.x];
        vs2[threadIdx.x] = g_v2[threadIdx.x];
    }
    __syncthreads();

    int t = blockIdx.x * blockDim.x + threadIdx.x;
    int d = t >> 4, l = t & 15;
    bool valid = (d < n);

    float acc = 0.f;
    if (valid) acc = gather_feat(g_ht2, d, l) * g_dinv[d];

    // broadcast the 16 per-feature sums to every lane of the group
    int base = (threadIdx.x & 31) & 16;   // group's base lane within the warp
    float a[16];
    #pragma unroll
    for (int k = 0; k < 16; k++)
        a[k] = __shfl_sync(0xffffffffu, acc, base + k, 32);

    if (!valid) return;

    // head scalars: lane 0 -> s1, lane 1 -> s2
    if (l == 0) {
        float s1 = g_c1;
        #pragma unroll
        for (int k = 0; k < 16; k++) s1 = fmaf(a[k], vs1[k], s1);
        g_s1[d] = s1;
    } else if (l == 1) {
        float s2 = g_c2;
        #pragma unroll
        for (int k = 0; k < 16; k++) s2 = fmaf(a[k], vs2[k], s2);
        g_s2[d] = s2;
    }

    // z columns [4l, 4l+4): one float4 per lane, coalesced across the group
    float4 accv = bs[l];
    #pragma unroll
    for (int k = 0; k < 16; k++) {
        float4 w = Ws[k * 16 + l];
        accv.x = fmaf(a[k], w.x, accv.x);
        accv.y = fmaf(a[k], w.y, accv.y);
        accv.z = fmaf(a[k], w.z, accv.z);
        accv.w = fmaf(a[k], w.w, accv.w);
    }
    ((float4*)(z + (size_t)d * 64))[l] = accv;
}

// -------- edge logits: s1[src] + s2[dst] + be ; also re-zero g_deg --------
__global__ void k_logits(const int* __restrict__ ps, const int* __restrict__ pd,
                         const int* __restrict__ ns, const int* __restrict__ nd,
                         const float* __restrict__ be, float* __restrict__ out,
                         int P, int Ng, int n) {
    int i = blockIdx.x * blockDim.x + threadIdx.x;
    if (i < n) g_deg[i] = 0;           // prepare next call (invariant: zero at entry)
    if (i >= P + Ng) return;
    unsigned s, d;
    if (i < P) { s = (unsigned)ps[i]; d = (unsigned)pd[i]; }
    else       { s = (unsigned)ns[i - P]; d = (unsigned)nd[i - P]; }
    float v = __ldg(be);
    if (s < (unsigned)n) v += g_s1[s];
    if (d < (unsigned)n) v += g_s2[d];
    out[i] = v;
}

extern "C" void kernel_launch(void* const* d_in, const int* in_sizes, int n_in,
                              void* d_out, int out_size) {
    const float* x  = (const float*)d_in[0];
    const float* W1 = (const float*)d_in[1];
    const float* b1 = (const float*)d_in[2];
    const float* W2 = (const float*)d_in[3];
    const float* b2 = (const float*)d_in[4];
    const float* We = (const float*)d_in[5];
    const float* be = (const float*)d_in[6];
    const int* ei = (const int*)d_in[7];   // edge_index int32 [2, E]
    const int* pe = (const int*)d_in[8];   // pos_edge_index int32 [2, P]
    const int* ne = (const int*)d_in[9];   // neg_edge_index int32 [2, Ng]

    int n  = in_sizes[0] / 512;
    int E  = in_sizes[7] / 2;
    int P  = in_sizes[8] / 2;
    int Ng = in_sizes[9] / 2;

    float* z = (float*)d_out;                 // [n, 64]
    float* logits = z + (size_t)n * 64;       // [P + Ng]

    const int* src = ei;
    const int* dst = ei + E;

    int nb  = (n + 255) / 256;
    int eb  = (E + 255) / 256;
    int gb  = (16 * n + 255) / 256;
    int lb  = (P + Ng + 255) / 256;

    // One-time stream/event setup (outside capture: first call is uncaptured).
    static cudaStream_t s1 = nullptr;
    static cudaEvent_t evFork = nullptr, evScan = nullptr, evScale = nullptr;
    if (s1 == nullptr) {
        cudaStreamCreateWithFlags(&s1, cudaStreamNonBlocking);
        cudaEventCreateWithFlags(&evFork, cudaEventDisableTiming);
        cudaEventCreateWithFlags(&evScan, cudaEventDisableTiming);
        cudaEventCreateWithFlags(&evScale, cudaEventDisableTiming);
    }

    // Fork at t=0: GEMM1 (raw h, no dinv dependency) on side stream.
    cudaEventRecord(evFork, 0);
    cudaStreamWaitEvent(s1, evFork, 0);
    k_gemm1<<<nb, 256, 0, s1>>>(x, W1, n);

    // Main stream: CSR build (g_deg zero on entry, invariant).
    k_deg_acc<<<eb, 256>>>(dst, E, n, W2, b2, We);
    k_scan1<<<nb, 256>>>(n);
    k_scan23<<<nb, 256>>>(n);
    cudaEventRecord(evScan, 0);               // dinv/starts ready
    k_fill<<<eb, 256>>>(src, dst, E, n);      // atomic-free

    // Side stream: scale (needs gemm1 done + dinv), overlaps fill.
    cudaStreamWaitEvent(s1, evScan, 0);
    k_scale<<<nb, 256, 0, s1>>>(n);
    cudaEventRecord(evScale, s1);

    // Join: gathers need scaled ht1 (side) and adj (fill, main-ordered).
    cudaStreamWaitEvent(0, evScale, 0);
    k_gather1<<<gb, 256>>>(b1, n);
    k_gather2<<<gb, 256>>>(W2, b2, z, n);
    k_logits<<<lb, 256>>>(pe, pe + P, ne, ne + Ng, be, logits, P, Ng, n);
}